// round 2
// baseline (speedup 1.0000x reference)
#include <cuda_runtime.h>
#include <math.h>

#define N_NODES 100000
#define N_EDGES 1600000
#define F_IN    128
#define HID     64
#define NCLS    40

// ---------------- scratch (no allocations allowed) ----------------
__device__ int   g_is64;
__device__ float g_deg [N_NODES];
__device__ float g_dinv[N_NODES];
__device__ int   g_src [N_EDGES];
__device__ int   g_dst [N_EDGES];
__device__ float g_w   [N_EDGES];
__device__ __align__(16) float g_h1[N_NODES * HID];   // x @ W1
__device__ __align__(16) float g_a1[N_NODES * HID];   // aggregated layer-1
__device__ __align__(16) float g_h2[N_NODES * NCLS];  // relu(a1+b1) @ W2

// ---------------- edge dtype sniffing ----------------
// If edge_index is int64 (little-endian, values < 2^31), every odd int32 word
// is 0. If int32 (random node ids), odds of 256 consecutive zeros ~ 0.
__global__ void k_detect(const int* __restrict__ ei32) {
    if (threadIdx.x == 0 && blockIdx.x == 0) {
        int nz = 0;
        for (int i = 0; i < 256; i++) nz += (ei32[2 * i + 1] != 0);
        g_is64 = (nz == 0) ? 1 : 0;
    }
}

__device__ __forceinline__ int edge_at(const void* ei, long long idx) {
    int v;
    if (g_is64) v = (int)((const long long*)ei)[idx];
    else        v = ((const int*)ei)[idx];
    // clamp: a wrong dtype guess must degrade to rel_err, not a fault
    return min(max(v, 0), N_NODES - 1);
}

// ---------------- degree / normalization prep ----------------
__global__ void k_deg_init() {
    int i = blockIdx.x * blockDim.x + threadIdx.x;
    if (i < N_NODES) g_deg[i] = 1.0f;   // self-loop
}

__global__ void k_deg_acc(const void* __restrict__ ei) {
    int e = blockIdx.x * blockDim.x + threadIdx.x;
    if (e < N_EDGES) atomicAdd(&g_deg[edge_at(ei, (long long)N_EDGES + e)], 1.0f);
}

__global__ void k_dinv() {
    int i = blockIdx.x * blockDim.x + threadIdx.x;
    if (i < N_NODES) g_dinv[i] = rsqrtf(g_deg[i]);
}

// int32 src/dst + per-edge norm weight, so both agg passes read 12B/edge
__global__ void k_edge_prep(const void* __restrict__ ei) {
    int e = blockIdx.x * blockDim.x + threadIdx.x;
    if (e < N_EDGES) {
        int s = edge_at(ei, e);
        int d = edge_at(ei, (long long)N_EDGES + e);
        g_src[e] = s;
        g_dst[e] = d;
        g_w[e]   = g_dinv[s] * g_dinv[d];
    }
}

// ---------------- GEMM1: h1 = x @ W1   (100000x128 @ 128x64) ----------------
__global__ void k_gemm1(const float* __restrict__ x, const float* __restrict__ W) {
    __shared__ __align__(16) float Xs[128 * 64];  // 32KB
    __shared__ __align__(16) float Ws[64 * 64];   // 16KB
    const int t  = threadIdx.x;
    const int tx = t & 15;     // cols 4*tx .. 4*tx+3
    const int ty = t >> 4;     // rows ty, ty+16, ..., ty+112
    const int row0 = blockIdx.x * 128;

    float acc[8][4];
#pragma unroll
    for (int r = 0; r < 8; r++)
#pragma unroll
        for (int c = 0; c < 4; c++) acc[r][c] = 0.0f;

    for (int kc = 0; kc < 2; kc++) {
#pragma unroll
        for (int j = 0; j < 8; j++) {
            int idx = t + j * 256;          // 0..2047
            int r   = idx >> 4;
            int kq  = idx & 15;
            float4 v = make_float4(0.f, 0.f, 0.f, 0.f);
            if (row0 + r < N_NODES)
                v = *(const float4*)&x[(size_t)(row0 + r) * F_IN + kc * 64 + kq * 4];
            *(float4*)&Xs[r * 64 + kq * 4] = v;
        }
#pragma unroll
        for (int j = 0; j < 4; j++) {
            int idx = t + j * 256;          // 0..1023
            int r   = idx >> 4;
            int kq  = idx & 15;
            *(float4*)&Ws[r * 64 + kq * 4] =
                *(const float4*)&W[(size_t)(kc * 64 + r) * HID + kq * 4];
        }
        __syncthreads();

#pragma unroll 4
        for (int k = 0; k < 64; k++) {
            float4 w = *(float4*)&Ws[k * 64 + tx * 4];
#pragma unroll
            for (int r = 0; r < 8; r++) {
                float xv = Xs[(ty + r * 16) * 64 + k];
                acc[r][0] = fmaf(xv, w.x, acc[r][0]);
                acc[r][1] = fmaf(xv, w.y, acc[r][1]);
                acc[r][2] = fmaf(xv, w.z, acc[r][2]);
                acc[r][3] = fmaf(xv, w.w, acc[r][3]);
            }
        }
        __syncthreads();
    }

#pragma unroll
    for (int r = 0; r < 8; r++) {
        int row = row0 + ty + r * 16;
        if (row < N_NODES)
            *(float4*)&g_h1[(size_t)row * HID + tx * 4] =
                make_float4(acc[r][0], acc[r][1], acc[r][2], acc[r][3]);
    }
}

// ---------------- aggregation layer 1 ----------------
__global__ void k_selfloop1() {
    int i = blockIdx.x * blockDim.x + threadIdx.x;   // over N*16 float4
    if (i < N_NODES * (HID / 4)) {
        int node = i >> 4;
        float w = g_dinv[node]; w *= w;
        float4 v = *(const float4*)&g_h1[(size_t)i * 4];
        v.x *= w; v.y *= w; v.z *= w; v.w *= w;
        *(float4*)&g_a1[(size_t)i * 4] = v;
    }
}

// warp per edge: gather h1[src] (float2/lane), scatter-add into a1[dst]
__global__ void k_agg1() {
    unsigned gid = blockIdx.x * blockDim.x + threadIdx.x;
    int e    = gid >> 5;
    int lane = threadIdx.x & 31;
    if (e < N_EDGES) {
        int   s = g_src[e];
        int   d = g_dst[e];
        float w = g_w[e];
        float2 v = *(const float2*)&g_h1[(size_t)s * HID + lane * 2];
        atomicAdd(&g_a1[(size_t)d * HID + lane * 2],     v.x * w);
        atomicAdd(&g_a1[(size_t)d * HID + lane * 2 + 1], v.y * w);
    }
}

// ---------------- GEMM2: h2 = relu(a1 + b1) @ W2  (100000x64 @ 64x40) ----------
__global__ void k_gemm2(const float* __restrict__ b1, const float* __restrict__ W2) {
    __shared__ float Ws[HID * NCLS];  // 10240B
    __shared__ float bs[HID];
    const int t = threadIdx.x;
#pragma unroll
    for (int j = 0; j < 10; j++) Ws[t + j * 256] = W2[t + j * 256];
    if (t < HID) bs[t] = b1[t];
    __syncthreads();

    const int rg = t >> 2;
    const int cg = t & 3;
    const int row0 = blockIdx.x * 256 + rg * 4;

    float acc[4][10];
#pragma unroll
    for (int r = 0; r < 4; r++)
#pragma unroll
        for (int c = 0; c < 10; c++) acc[r][c] = 0.0f;

    for (int k = 0; k < HID; k++) {
        float wv[10];
#pragma unroll
        for (int c = 0; c < 10; c++) wv[c] = Ws[k * NCLS + cg * 10 + c];
        float bk = bs[k];
#pragma unroll
        for (int r = 0; r < 4; r++) {
            int row = row0 + r;
            float a = 0.0f;
            if (row < N_NODES)
                a = fmaxf(g_a1[(size_t)row * HID + k] + bk, 0.0f);
#pragma unroll
            for (int c = 0; c < 10; c++) acc[r][c] = fmaf(a, wv[c], acc[r][c]);
        }
    }
#pragma unroll
    for (int r = 0; r < 4; r++) {
        int row = row0 + r;
        if (row < N_NODES)
#pragma unroll
            for (int c = 0; c < 10; c++)
                g_h2[(size_t)row * NCLS + cg * 10 + c] = acc[r][c];
    }
}

// ---------------- aggregation layer 2 (into d_out) ----------------
__global__ void k_selfloop2(float* __restrict__ out) {
    int i = blockIdx.x * blockDim.x + threadIdx.x;
    if (i < N_NODES * NCLS) {
        int node = i / NCLS;
        float w = g_dinv[node]; w *= w;
        out[i] = g_h2[i] * w;
    }
}

__global__ void k_agg2(float* __restrict__ out) {
    unsigned gid = blockIdx.x * blockDim.x + threadIdx.x;
    int e    = gid >> 5;
    int lane = threadIdx.x & 31;
    if (e < N_EDGES) {
        int   s = g_src[e];
        int   d = g_dst[e];
        float w = g_w[e];
        float v0 = g_h2[(size_t)s * NCLS + lane] * w;
        atomicAdd(&out[(size_t)d * NCLS + lane], v0);
        if (lane < 8) {
            float v1 = g_h2[(size_t)s * NCLS + 32 + lane] * w;
            atomicAdd(&out[(size_t)d * NCLS + 32 + lane], v1);
        }
    }
}

// ---------------- bias + log_softmax (in place on d_out) ----------------
__global__ void k_logsoftmax(float* __restrict__ out, const float* __restrict__ b2) {
    unsigned gid = blockIdx.x * blockDim.x + threadIdx.x;
    int n    = gid >> 5;
    int lane = threadIdx.x & 31;
    if (n < N_NODES) {
        const float NEG_INF = __int_as_float(0xff800000);
        float z0 = out[(size_t)n * NCLS + lane] + b2[lane];
        float z1 = NEG_INF;
        if (lane < 8) z1 = out[(size_t)n * NCLS + 32 + lane] + b2[32 + lane];

        float m = fmaxf(z0, z1);
#pragma unroll
        for (int off = 16; off > 0; off >>= 1)
            m = fmaxf(m, __shfl_xor_sync(0xffffffffu, m, off));

        float s = __expf(z0 - m) + ((lane < 8) ? __expf(z1 - m) : 0.0f);
#pragma unroll
        for (int off = 16; off > 0; off >>= 1)
            s += __shfl_xor_sync(0xffffffffu, s, off);

        float lse = m + __logf(s);
        out[(size_t)n * NCLS + lane] = z0 - lse;
        if (lane < 8) out[(size_t)n * NCLS + 32 + lane] = z1 - lse;
    }
}

// ---------------- launch ----------------
extern "C" void kernel_launch(void* const* d_in, const int* in_sizes, int n_in,
                              void* d_out, int out_size) {
    // Resolve inputs by element count (all distinct) instead of trusting order.
    const float* x  = nullptr;  const void* ei = nullptr;
    const float* W1 = nullptr;  const float* b1 = nullptr;
    const float* W2 = nullptr;  const float* b2 = nullptr;
    for (int i = 0; i < n_in; i++) {
        switch (in_sizes[i]) {
            case N_NODES * F_IN:  x  = (const float*)d_in[i]; break;  // 12.8M
            case 2 * N_EDGES:     ei = d_in[i];               break;  // 3.2M
            case F_IN * HID:      W1 = (const float*)d_in[i]; break;  // 8192
            case HID:             b1 = (const float*)d_in[i]; break;  // 64
            case HID * NCLS:      W2 = (const float*)d_in[i]; break;  // 2560
            case NCLS:            b2 = (const float*)d_in[i]; break;  // 40
            default: break;
        }
    }
    float* out = (float*)d_out;

    k_detect   <<<1, 32>>>((const int*)ei);
    k_deg_init <<<(N_NODES + 255) / 256, 256>>>();
    k_deg_acc  <<<(N_EDGES + 255) / 256, 256>>>(ei);
    k_dinv     <<<(N_NODES + 255) / 256, 256>>>();
    k_edge_prep<<<(N_EDGES + 255) / 256, 256>>>(ei);

    k_gemm1    <<<(N_NODES + 127) / 128, 256>>>(x, W1);
    k_selfloop1<<<(N_NODES * (HID / 4) + 255) / 256, 256>>>();
    k_agg1     <<<(N_EDGES * 32) / 256, 256>>>();

    k_gemm2    <<<(N_NODES + 255) / 256, 256>>>(b1, W2);
    k_selfloop2<<<(N_NODES * NCLS + 255) / 256, 256>>>(out);
    k_agg2     <<<(N_EDGES * 32) / 256, 256>>>(out);

    k_logsoftmax<<<(N_NODES * 32) / 256, 256>>>(out, b2);
}

// round 3
// speedup vs baseline: 2.1562x; 2.1562x over previous
#include <cuda_runtime.h>
#include <math.h>

#define N_NODES 100000
#define N_EDGES 1600000
#define F_IN    128
#define HID     64
#define NCLS    40
#define SCAN_B  512
#define N_SCANB ((N_NODES + SCAN_B - 1) / SCAN_B)   // 196

// ---------------- scratch (no allocations allowed) ----------------
__device__ int   g_is64;
__device__ int   g_cnt [N_NODES];        // in-degree histogram (no self-loop)
__device__ int   g_off [N_NODES + 1];    // CSR row offsets (by dst)
__device__ int   g_cur [N_NODES];        // scatter cursors
__device__ int   g_bsum [256];
__device__ int   g_bsumx[256];
__device__ float g_dinv[N_NODES];
__device__ int   g_csr_src[N_EDGES];     // src per CSR slot
__device__ float g_csr_w  [N_EDGES];     // norm weight per CSR slot
__device__ __align__(16) float g_h1[N_NODES * HID];   // x @ W1
__device__ __align__(16) float g_a1[N_NODES * HID];   // aggregated layer-1
__device__ __align__(16) float g_h2[N_NODES * NCLS];  // relu(a1+b1) @ W2

// ---------------- edge dtype sniffing ----------------
__global__ void k_detect(const int* __restrict__ ei32) {
    if (threadIdx.x == 0 && blockIdx.x == 0) {
        int nz = 0;
        for (int i = 0; i < 256; i++) nz += (ei32[2 * i + 1] != 0);
        g_is64 = (nz == 0) ? 1 : 0;
    }
}

__device__ __forceinline__ int edge_at(const void* ei, long long idx) {
    int v;
    if (g_is64) v = (int)((const long long*)ei)[idx];
    else        v = ((const int*)ei)[idx];
    return min(max(v, 0), N_NODES - 1);   // wrong guess -> rel_err, not fault
}

// ---------------- CSR build ----------------
__global__ void k_zero() {
    int i = blockIdx.x * blockDim.x + threadIdx.x;
    if (i < N_NODES) g_cnt[i] = 0;
}

__global__ void k_hist(const void* __restrict__ ei) {
    int e = blockIdx.x * blockDim.x + threadIdx.x;
    if (e < N_EDGES) atomicAdd(&g_cnt[edge_at(ei, (long long)N_EDGES + e)], 1);
}

// block-level exclusive scan (Hillis-Steele), 512 elems/block
__global__ void k_scan_block() {
    __shared__ int sh[SCAN_B];
    int i = blockIdx.x * SCAN_B + threadIdx.x;
    int v = (i < N_NODES) ? g_cnt[i] : 0;
    sh[threadIdx.x] = v;
    __syncthreads();
#pragma unroll
    for (int off = 1; off < SCAN_B; off <<= 1) {
        int t = (threadIdx.x >= off) ? sh[threadIdx.x - off] : 0;
        __syncthreads();
        sh[threadIdx.x] += t;
        __syncthreads();
    }
    if (i < N_NODES) g_off[i] = sh[threadIdx.x] - v;       // exclusive
    if (threadIdx.x == SCAN_B - 1) g_bsum[blockIdx.x] = sh[SCAN_B - 1];
}

__global__ void k_scan_top() {   // 256 threads, scans N_SCANB block sums
    __shared__ int sh[256];
    int v = (threadIdx.x < N_SCANB) ? g_bsum[threadIdx.x] : 0;
    sh[threadIdx.x] = v;
    __syncthreads();
#pragma unroll
    for (int off = 1; off < 256; off <<= 1) {
        int t = (threadIdx.x >= off) ? sh[threadIdx.x - off] : 0;
        __syncthreads();
        sh[threadIdx.x] += t;
        __syncthreads();
    }
    g_bsumx[threadIdx.x] = sh[threadIdx.x] - v;            // exclusive
}

__global__ void k_scan_add() {
    int i = blockIdx.x * blockDim.x + threadIdx.x;
    if (i < N_NODES) g_off[i] += g_bsumx[i >> 9];
    if (i == 0) g_off[N_NODES] = N_EDGES;
}

__global__ void k_dinv() {   // deg = in-edges + self-loop; also zero cursors
    int i = blockIdx.x * blockDim.x + threadIdx.x;
    if (i < N_NODES) {
        g_dinv[i] = rsqrtf((float)(g_cnt[i] + 1));
        g_cur[i]  = 0;
    }
}

__global__ void k_scatter(const void* __restrict__ ei) {
    int e = blockIdx.x * blockDim.x + threadIdx.x;
    if (e < N_EDGES) {
        int s = edge_at(ei, e);
        int d = edge_at(ei, (long long)N_EDGES + e);
        int pos = g_off[d] + atomicAdd(&g_cur[d], 1);
        g_csr_src[pos] = s;
        g_csr_w[pos]   = g_dinv[s] * g_dinv[d];
    }
}

// ---------------- GEMM1: h1 = x @ W1   (100000x128 @ 128x64) ----------------
__global__ void k_gemm1(const float* __restrict__ x, const float* __restrict__ W) {
    __shared__ __align__(16) float Xs[128 * 64];  // 32KB
    __shared__ __align__(16) float Ws[64 * 64];   // 16KB
    const int t  = threadIdx.x;
    const int tx = t & 15;
    const int ty = t >> 4;
    const int row0 = blockIdx.x * 128;

    float acc[8][4];
#pragma unroll
    for (int r = 0; r < 8; r++)
#pragma unroll
        for (int c = 0; c < 4; c++) acc[r][c] = 0.0f;

    for (int kc = 0; kc < 2; kc++) {
#pragma unroll
        for (int j = 0; j < 8; j++) {
            int idx = t + j * 256;
            int r   = idx >> 4;
            int kq  = idx & 15;
            float4 v = make_float4(0.f, 0.f, 0.f, 0.f);
            if (row0 + r < N_NODES)
                v = *(const float4*)&x[(size_t)(row0 + r) * F_IN + kc * 64 + kq * 4];
            *(float4*)&Xs[r * 64 + kq * 4] = v;
        }
#pragma unroll
        for (int j = 0; j < 4; j++) {
            int idx = t + j * 256;
            int r   = idx >> 4;
            int kq  = idx & 15;
            *(float4*)&Ws[r * 64 + kq * 4] =
                *(const float4*)&W[(size_t)(kc * 64 + r) * HID + kq * 4];
        }
        __syncthreads();

#pragma unroll 4
        for (int k = 0; k < 64; k++) {
            float4 w = *(float4*)&Ws[k * 64 + tx * 4];
#pragma unroll
            for (int r = 0; r < 8; r++) {
                float xv = Xs[(ty + r * 16) * 64 + k];
                acc[r][0] = fmaf(xv, w.x, acc[r][0]);
                acc[r][1] = fmaf(xv, w.y, acc[r][1]);
                acc[r][2] = fmaf(xv, w.z, acc[r][2]);
                acc[r][3] = fmaf(xv, w.w, acc[r][3]);
            }
        }
        __syncthreads();
    }

#pragma unroll
    for (int r = 0; r < 8; r++) {
        int row = row0 + ty + r * 16;
        if (row < N_NODES)
            *(float4*)&g_h1[(size_t)row * HID + tx * 4] =
                make_float4(acc[r][0], acc[r][1], acc[r][2], acc[r][3]);
    }
}

// ---------------- aggregation layer 1: warp per dst node, CSR gather --------
__global__ void k_agg1() {
    unsigned gid = blockIdx.x * blockDim.x + threadIdx.x;
    int n    = gid >> 5;
    int lane = threadIdx.x & 31;
    if (n >= N_NODES) return;

    int beg = g_off[n], end = g_off[n + 1];
    float ws = g_dinv[n]; ws *= ws;

    float2 v = *(const float2*)&g_h1[(size_t)n * HID + lane * 2];
    float ax = v.x * ws, ay = v.y * ws;

    int e = beg;
    for (; e + 3 < end; e += 4) {
        int   s0 = g_csr_src[e],     s1 = g_csr_src[e + 1];
        int   s2 = g_csr_src[e + 2], s3 = g_csr_src[e + 3];
        float w0 = g_csr_w[e],       w1 = g_csr_w[e + 1];
        float w2 = g_csr_w[e + 2],   w3 = g_csr_w[e + 3];
        float2 v0 = *(const float2*)&g_h1[(size_t)s0 * HID + lane * 2];
        float2 v1 = *(const float2*)&g_h1[(size_t)s1 * HID + lane * 2];
        float2 v2 = *(const float2*)&g_h1[(size_t)s2 * HID + lane * 2];
        float2 v3 = *(const float2*)&g_h1[(size_t)s3 * HID + lane * 2];
        ax = fmaf(v0.x, w0, ax); ay = fmaf(v0.y, w0, ay);
        ax = fmaf(v1.x, w1, ax); ay = fmaf(v1.y, w1, ay);
        ax = fmaf(v2.x, w2, ax); ay = fmaf(v2.y, w2, ay);
        ax = fmaf(v3.x, w3, ax); ay = fmaf(v3.y, w3, ay);
    }
    for (; e < end; e++) {
        int   s = g_csr_src[e];
        float w = g_csr_w[e];
        float2 vv = *(const float2*)&g_h1[(size_t)s * HID + lane * 2];
        ax = fmaf(vv.x, w, ax); ay = fmaf(vv.y, w, ay);
    }
    *(float2*)&g_a1[(size_t)n * HID + lane * 2] = make_float2(ax, ay);
}

// ---------------- GEMM2: h2 = relu(a1 + b1) @ W2  (100000x64 @ 64x40) -------
__global__ void k_gemm2(const float* __restrict__ b1, const float* __restrict__ W2) {
    __shared__ float Ws[HID * NCLS];
    __shared__ float bs[HID];
    const int t = threadIdx.x;
#pragma unroll
    for (int j = 0; j < 10; j++) Ws[t + j * 256] = W2[t + j * 256];
    if (t < HID) bs[t] = b1[t];
    __syncthreads();

    const int rg = t >> 2;
    const int cg = t & 3;
    const int row0 = blockIdx.x * 256 + rg * 4;

    float acc[4][10];
#pragma unroll
    for (int r = 0; r < 4; r++)
#pragma unroll
        for (int c = 0; c < 10; c++) acc[r][c] = 0.0f;

    for (int k = 0; k < HID; k++) {
        float wv[10];
#pragma unroll
        for (int c = 0; c < 10; c++) wv[c] = Ws[k * NCLS + cg * 10 + c];
        float bk = bs[k];
#pragma unroll
        for (int r = 0; r < 4; r++) {
            int row = row0 + r;
            float a = 0.0f;
            if (row < N_NODES)
                a = fmaxf(g_a1[(size_t)row * HID + k] + bk, 0.0f);
#pragma unroll
            for (int c = 0; c < 10; c++) acc[r][c] = fmaf(a, wv[c], acc[r][c]);
        }
    }
#pragma unroll
    for (int r = 0; r < 4; r++) {
        int row = row0 + r;
        if (row < N_NODES)
#pragma unroll
            for (int c = 0; c < 10; c++)
                g_h2[(size_t)row * NCLS + cg * 10 + c] = acc[r][c];
    }
}

// ------- aggregation layer 2 + bias + log_softmax, warp per node, fused -----
__global__ void k_agg2_softmax(float* __restrict__ out, const float* __restrict__ b2) {
    unsigned gid = blockIdx.x * blockDim.x + threadIdx.x;
    int n    = gid >> 5;
    int lane = threadIdx.x & 31;
    if (n >= N_NODES) return;

    int beg = g_off[n], end = g_off[n + 1];
    float ws = g_dinv[n]; ws *= ws;

    float a0 = g_h2[(size_t)n * NCLS + lane] * ws;
    float a1v = (lane < 8) ? g_h2[(size_t)n * NCLS + 32 + lane] * ws : 0.0f;

    int e = beg;
    for (; e + 1 < end; e += 2) {
        int   s0 = g_csr_src[e],   s1 = g_csr_src[e + 1];
        float w0 = g_csr_w[e],     w1 = g_csr_w[e + 1];
        float v0 = g_h2[(size_t)s0 * NCLS + lane];
        float v1 = g_h2[(size_t)s1 * NCLS + lane];
        a0 = fmaf(v0, w0, a0);
        a0 = fmaf(v1, w1, a0);
        if (lane < 8) {
            float u0 = g_h2[(size_t)s0 * NCLS + 32 + lane];
            float u1 = g_h2[(size_t)s1 * NCLS + 32 + lane];
            a1v = fmaf(u0, w0, a1v);
            a1v = fmaf(u1, w1, a1v);
        }
    }
    for (; e < end; e++) {
        int   s = g_csr_src[e];
        float w = g_csr_w[e];
        a0 = fmaf(g_h2[(size_t)s * NCLS + lane], w, a0);
        if (lane < 8) a1v = fmaf(g_h2[(size_t)s * NCLS + 32 + lane], w, a1v);
    }

    // bias + log_softmax over 40 logits held across the warp
    const float NEG_INF = __int_as_float(0xff800000);
    float z0 = a0 + b2[lane];
    float z1 = (lane < 8) ? a1v + b2[32 + lane] : NEG_INF;

    float m = fmaxf(z0, z1);
#pragma unroll
    for (int off = 16; off > 0; off >>= 1)
        m = fmaxf(m, __shfl_xor_sync(0xffffffffu, m, off));

    float s = __expf(z0 - m) + ((lane < 8) ? __expf(z1 - m) : 0.0f);
#pragma unroll
    for (int off = 16; off > 0; off >>= 1)
        s += __shfl_xor_sync(0xffffffffu, s, off);

    float lse = m + __logf(s);
    out[(size_t)n * NCLS + lane] = z0 - lse;
    if (lane < 8) out[(size_t)n * NCLS + 32 + lane] = z1 - lse;
}

// ---------------- launch ----------------
extern "C" void kernel_launch(void* const* d_in, const int* in_sizes, int n_in,
                              void* d_out, int out_size) {
    const float* x  = nullptr;  const void* ei = nullptr;
    const float* W1 = nullptr;  const float* b1 = nullptr;
    const float* W2 = nullptr;  const float* b2 = nullptr;
    for (int i = 0; i < n_in; i++) {
        switch (in_sizes[i]) {
            case N_NODES * F_IN:  x  = (const float*)d_in[i]; break;
            case 2 * N_EDGES:     ei = d_in[i];               break;
            case F_IN * HID:      W1 = (const float*)d_in[i]; break;
            case HID:             b1 = (const float*)d_in[i]; break;
            case HID * NCLS:      W2 = (const float*)d_in[i]; break;
            case NCLS:            b2 = (const float*)d_in[i]; break;
            default: break;
        }
    }
    float* out = (float*)d_out;

    const int NB_N = (N_NODES + 255) / 256;
    const int NB_E = (N_EDGES + 255) / 256;
    const int NB_W = (N_NODES * 32 + 255) / 256;   // warp per node

    k_detect     <<<1, 32>>>((const int*)ei);
    k_zero       <<<NB_N, 256>>>();
    k_hist       <<<NB_E, 256>>>(ei);
    k_scan_block <<<N_SCANB, SCAN_B>>>();
    k_scan_top   <<<1, 256>>>();
    k_scan_add   <<<NB_N, 256>>>();
    k_dinv       <<<NB_N, 256>>>();
    k_scatter    <<<NB_E, 256>>>(ei);

    k_gemm1      <<<(N_NODES + 127) / 128, 256>>>(x, W1);
    k_agg1       <<<NB_W, 256>>>();
    k_gemm2      <<<NB_N, 256>>>(b1, W2);
    k_agg2_softmax<<<NB_W, 256>>>(out, b2);
}